// round 14
// baseline (speedup 1.0000x reference)
#include <cuda_runtime.h>
#include <cstdint>

// Scratch: per-node projection (pu0, pu1, pv0, pv1). 50000 * 16B = 800 KB.
#define MAX_NODES 131072
__device__ float4 g_node_proj[MAX_NODES];

// Device-wide barrier ticket counter (epoch-based: safe across graph replays).
__device__ unsigned long long g_bar;

#define D_DIM 128
#define E_DIM 64
#define FULLMASK 0xffffffffu

// Per-warp pipeline geometry: each warp owns STAGES private 16-edge tiles.
#define WTILE_EDGES 16
#define WTILE_BYTES (WTILE_EDGES * E_DIM * 4)   // 4096
#define STAGES 3
#define WARPS 8
#define SMEM_DATA_BYTES (WARPS * STAGES * WTILE_BYTES)  // 96 KB
#define SMEM_MBAR_OFF SMEM_DATA_BYTES
#define SMEM_TOTAL (SMEM_MBAR_OFF + WARPS * STAGES * 8)

// ---------------------------------------------------------------------------
// PTX helpers
__device__ __forceinline__ uint32_t smem_u32(const void* p) {
    return (uint32_t)__cvta_generic_to_shared(p);
}
__device__ __forceinline__ void mbar_init(uint32_t mbar, uint32_t count) {
    asm volatile("mbarrier.init.shared.b64 [%0], %1;" :: "r"(mbar), "r"(count) : "memory");
}
__device__ __forceinline__ void mbar_expect_tx(uint32_t mbar, uint32_t bytes) {
    asm volatile("mbarrier.arrive.expect_tx.shared.b64 _, [%0], %1;"
                 :: "r"(mbar), "r"(bytes) : "memory");
}
__device__ __forceinline__ void mbar_wait(uint32_t mbar, uint32_t parity) {
    asm volatile(
        "{\n\t"
        ".reg .pred P;\n\t"
        "WAIT_%=:\n\t"
        "mbarrier.try_wait.parity.acquire.cta.shared::cta.b64 P, [%0], %1, 0x989680;\n\t"
        "@!P bra WAIT_%=;\n\t"
        "}"
        :: "r"(mbar), "r"(parity) : "memory");
}
__device__ __forceinline__ void bulk_copy_g2s(uint32_t sdst, const void* gsrc,
                                              uint32_t bytes, uint32_t mbar) {
    asm volatile(
        "cp.async.bulk.shared::cta.global.mbarrier::complete_tx::bytes [%0], [%1], %2, [%3];"
        :: "r"(sdst), "l"(gsrc), "r"(bytes), "r"(mbar) : "memory");
}

// ---------------------------------------------------------------------------
__device__ __forceinline__ void dot16(float& s0, float& s1,
                                      const float4& v0, const float4& v1,
                                      const float4& v2, const float4& v3,
                                      const float2* __restrict__ w) {
    float x0, x1, y0, y1;
    x0 = v0.x * w[0].x;              x1 = v0.x * w[0].y;
    y0 = v2.x * w[8].x;              y1 = v2.x * w[8].y;
    x0 = fmaf(v0.y, w[1].x, x0);     x1 = fmaf(v0.y, w[1].y, x1);
    y0 = fmaf(v2.y, w[9].x, y0);     y1 = fmaf(v2.y, w[9].y, y1);
    x0 = fmaf(v0.z, w[2].x, x0);     x1 = fmaf(v0.z, w[2].y, x1);
    y0 = fmaf(v2.z, w[10].x, y0);    y1 = fmaf(v2.z, w[10].y, y1);
    x0 = fmaf(v0.w, w[3].x, x0);     x1 = fmaf(v0.w, w[3].y, x1);
    y0 = fmaf(v2.w, w[11].x, y0);    y1 = fmaf(v2.w, w[11].y, y1);
    x0 = fmaf(v1.x, w[4].x, x0);     x1 = fmaf(v1.x, w[4].y, x1);
    y0 = fmaf(v3.x, w[12].x, y0);    y1 = fmaf(v3.x, w[12].y, y1);
    x0 = fmaf(v1.y, w[5].x, x0);     x1 = fmaf(v1.y, w[5].y, x1);
    y0 = fmaf(v3.y, w[13].x, y0);    y1 = fmaf(v3.y, w[13].y, y1);
    x0 = fmaf(v1.z, w[6].x, x0);     x1 = fmaf(v1.z, w[6].y, x1);
    y0 = fmaf(v3.z, w[14].x, y0);    y1 = fmaf(v3.z, w[14].y, y1);
    x0 = fmaf(v1.w, w[7].x, x0);     x1 = fmaf(v1.w, w[7].y, x1);
    y0 = fmaf(v3.w, w[15].x, y0);    y1 = fmaf(v3.w, w[15].y, y1);
    s0 = x0 + y0;
    s1 = x1 + y1;
}

// ---------------------------------------------------------------------------
// Fused kernel:
//   Phase 0: mbarrier init + edge TMA prologue (independent of node proj).
//   Phase 1: node projection (grid-strided, 16 lanes/node).
//   Device-wide epoch barrier.
//   Phase 2: per-warp TMA-pipelined edge scoring (R13 layout).
__global__ __launch_bounds__(256, 2)
void fused_kernel(const float* __restrict__ nf,
                  const float* __restrict__ ef,
                  const int* __restrict__ src,
                  const int* __restrict__ dst,
                  const float* __restrict__ W,
                  const float* __restrict__ b,
                  float* __restrict__ outf,
                  int n_nodes, int n_edges, int n_wtiles) {
    extern __shared__ char smem[];
    const uint32_t smem_base = smem_u32(smem);

    const int tid = threadIdx.x;
    const int warp = tid >> 5;
    const int lane = tid & 31;
    const int last = n_edges - 1;

    const uint32_t wdata = smem_base + (uint32_t)(warp * STAGES) * WTILE_BYTES;
    const uint32_t wmbar = smem_base + SMEM_MBAR_OFF + (uint32_t)(warp * STAGES) * 8;

    // ---- Phase 0: mbarrier init + edge prologue TMA (no proj dependency) ----
    if (tid < WARPS * STAGES)
        mbar_init(smem_base + SMEM_MBAR_OFF + tid * 8, 1);
    __syncthreads();

    const int stream = blockIdx.x * WARPS + warp;
    const int NS = gridDim.x * WARPS;
    int K = 0;
    for (int t = stream; t < n_wtiles; t += NS) K++;

    if (lane == 0) {
#pragma unroll
        for (int j = 0; j < STAGES; j++) {
            if (j < K) {
                int t = stream + j * NS;
                long long rem = (long long)n_edges - (long long)t * WTILE_EDGES;
                uint32_t bytes = rem >= WTILE_EDGES
                    ? (uint32_t)WTILE_BYTES : (uint32_t)(rem * E_DIM * 4);
                mbar_expect_tx(wmbar + 8 * j, bytes);
                bulk_copy_g2s(wdata + j * WTILE_BYTES,
                              ef + (size_t)t * WTILE_EDGES * E_DIM,
                              bytes, wmbar + 8 * j);
            }
        }
    }

    // ---- Phase 1: node projection (R9 math), grid-strided ----
    {
        const int lane16 = tid & 15;
        const int ng = tid >> 4;  // 0..15 node slot within block
        const float2* W2 = reinterpret_cast<const float2*>(W);

        float4 wu_lo0 = *reinterpret_cast<const float4*>(&W2[4 * lane16]);
        float4 wu_lo1 = *reinterpret_cast<const float4*>(&W2[4 * lane16 + 2]);
        float4 wu_hi0 = *reinterpret_cast<const float4*>(&W2[64 + 4 * lane16]);
        float4 wu_hi1 = *reinterpret_cast<const float4*>(&W2[64 + 4 * lane16 + 2]);
        float4 wv_lo0 = *reinterpret_cast<const float4*>(&W2[128 + 4 * lane16]);
        float4 wv_lo1 = *reinterpret_cast<const float4*>(&W2[128 + 4 * lane16 + 2]);
        float4 wv_hi0 = *reinterpret_cast<const float4*>(&W2[192 + 4 * lane16]);
        float4 wv_hi1 = *reinterpret_cast<const float4*>(&W2[192 + 4 * lane16 + 2]);

        for (int base = blockIdx.x * 16; base < n_nodes; base += gridDim.x * 16) {
            int node = base + ng;
            bool valid = (node < n_nodes);
            int node_c = valid ? node : (n_nodes - 1);

            const float4* row =
                reinterpret_cast<const float4*>(nf + (size_t)node_c * D_DIM);
            float4 a = __ldcs(row + lane16);
            float4 c = __ldcs(row + lane16 + 16);

            float pu0, pu1, pv0, pv1;
            pu0 = a.x * wu_lo0.x;            pu1 = a.x * wu_lo0.y;
            pv0 = a.x * wv_lo0.x;            pv1 = a.x * wv_lo0.y;
            pu0 = fmaf(a.y, wu_lo0.z, pu0);  pu1 = fmaf(a.y, wu_lo0.w, pu1);
            pv0 = fmaf(a.y, wv_lo0.z, pv0);  pv1 = fmaf(a.y, wv_lo0.w, pv1);
            pu0 = fmaf(a.z, wu_lo1.x, pu0);  pu1 = fmaf(a.z, wu_lo1.y, pu1);
            pv0 = fmaf(a.z, wv_lo1.x, pv0);  pv1 = fmaf(a.z, wv_lo1.y, pv1);
            pu0 = fmaf(a.w, wu_lo1.z, pu0);  pu1 = fmaf(a.w, wu_lo1.w, pu1);
            pv0 = fmaf(a.w, wv_lo1.z, pv0);  pv1 = fmaf(a.w, wv_lo1.w, pv1);
            pu0 = fmaf(c.x, wu_hi0.x, pu0);  pu1 = fmaf(c.x, wu_hi0.y, pu1);
            pv0 = fmaf(c.x, wv_hi0.x, pv0);  pv1 = fmaf(c.x, wv_hi0.y, pv1);
            pu0 = fmaf(c.y, wu_hi0.z, pu0);  pu1 = fmaf(c.y, wu_hi0.w, pu1);
            pv0 = fmaf(c.y, wv_hi0.z, pv0);  pv1 = fmaf(c.y, wv_hi0.w, pv1);
            pu0 = fmaf(c.z, wu_hi1.x, pu0);  pu1 = fmaf(c.z, wu_hi1.y, pu1);
            pv0 = fmaf(c.z, wv_hi1.x, pv0);  pv1 = fmaf(c.z, wv_hi1.y, pv1);
            pu0 = fmaf(c.w, wu_hi1.z, pu0);  pu1 = fmaf(c.w, wu_hi1.w, pu1);
            pv0 = fmaf(c.w, wv_hi1.z, pv0);  pv1 = fmaf(c.w, wv_hi1.w, pv1);

            int l1 = lane16 & 1;
            int l2 = lane16 & 2;
            float sendu = l1 ? pu0 : pu1;
            float keepu = l1 ? pu1 : pu0;
            float ru = keepu + __shfl_xor_sync(FULLMASK, sendu, 1);
            float sendv = l1 ? pv0 : pv1;
            float keepv = l1 ? pv1 : pv0;
            float rv = keepv + __shfl_xor_sync(FULLMASK, sendv, 1);
            float send2 = l2 ? ru : rv;
            float keep2 = l2 ? rv : ru;
            float r = keep2 + __shfl_xor_sync(FULLMASK, send2, 2);
            r += __shfl_xor_sync(FULLMASK, r, 4);
            r += __shfl_xor_sync(FULLMASK, r, 8);

            if (valid && lane16 < 4)
                reinterpret_cast<float*>(&g_node_proj[node])[lane16] = r;
        }
    }

    // ---- Device-wide epoch barrier (all blocks co-resident: 2/SM, 1 wave) ----
    __syncthreads();
    if (tid == 0) {
        __threadfence();  // release proj writes
        unsigned long long ticket = atomicAdd(&g_bar, 1ULL);
        unsigned long long target =
            (ticket / (unsigned long long)gridDim.x + 1ULL) *
            (unsigned long long)gridDim.x;
        while (atomicAdd(&g_bar, 0ULL) < target) {
            __nanosleep(64);
        }
        __threadfence();  // acquire
    }
    __syncthreads();

    // ---- Phase 2: edge scoring (R13 per-warp pipeline) ----
    if (K == 0) return;

    const int g8 = lane >> 2;
    const int lane4 = lane & 3;
    const int lv = lane4 & 1;

    const float2* W2 = reinterpret_cast<const float2*>(W);
    float2 w[16];
#pragma unroll
    for (int i = 0; i < 4; i++) {
        int kb = 2 * D_DIM + 4 * (lane4 + 4 * i);
        float4 p0 = *reinterpret_cast<const float4*>(&W2[kb]);
        float4 p1 = *reinterpret_cast<const float4*>(&W2[kb + 2]);
        w[4 * i + 0] = make_float2(p0.x, p0.y);
        w[4 * i + 1] = make_float2(p0.z, p0.w);
        w[4 * i + 2] = make_float2(p1.x, p1.y);
        w[4 * i + 3] = make_float2(p1.z, p1.w);
    }
    const float bsel = lv ? b[1] : b[0];

    int base0 = stream * WTILE_EDGES;
    int eA0 = base0 + g8;
    int eB0 = base0 + g8 + 8;
    int ecA = eA0 > last ? last : eA0;
    int ecB = eB0 > last ? last : eB0;
    int siA = src[ecA], diA = dst[ecA];
    int siB = src[ecB], diB = dst[ecB];

    int stage = 0;
    uint32_t parity = 0;
    for (int k = 0; k < K; k++) {
        int t = stream + k * NS;
        int eA = t * WTILE_EDGES + g8;
        int eB = eA + 8;

        float puA = reinterpret_cast<const float*>(&g_node_proj[siA])[lv];
        float pvA = reinterpret_cast<const float*>(&g_node_proj[diA])[2 + lv];
        float puB = reinterpret_cast<const float*>(&g_node_proj[siB])[lv];
        float pvB = reinterpret_cast<const float*>(&g_node_proj[diB])[2 + lv];
        if (k + 1 < K) {
            int bn = (t + NS) * WTILE_EDGES;
            int enA = bn + g8;
            int enB = bn + g8 + 8;
            int ecnA = enA > last ? last : enA;
            int ecnB = enB > last ? last : enB;
            siA = src[ecnA]; diA = dst[ecnA];
            siB = src[ecnB]; diB = dst[ecnB];
        }

        mbar_wait(wmbar + 8 * stage, parity);

        const char* tpA = smem + (size_t)(warp * STAGES + stage) * WTILE_BYTES
                          + g8 * (E_DIM * 4) + lane4 * 16;
        const char* tpB = tpA + 8 * (E_DIM * 4);
        float4 a0 = *reinterpret_cast<const float4*>(tpA);
        float4 a1 = *reinterpret_cast<const float4*>(tpA + 64);
        float4 a2 = *reinterpret_cast<const float4*>(tpA + 128);
        float4 a3 = *reinterpret_cast<const float4*>(tpA + 192);
        float4 c0 = *reinterpret_cast<const float4*>(tpB);
        float4 c1 = *reinterpret_cast<const float4*>(tpB + 64);
        float4 c2 = *reinterpret_cast<const float4*>(tpB + 128);
        float4 c3 = *reinterpret_cast<const float4*>(tpB + 192);

        float s0, s1;
        dot16(s0, s1, a0, a1, a2, a3, w);
        float sendA = lv ? s0 : s1;
        float keepA = lv ? s1 : s0;
        float rA = keepA + __shfl_xor_sync(FULLMASK, sendA, 1);
        rA += __shfl_xor_sync(FULLMASK, rA, 2);

        dot16(s0, s1, c0, c1, c2, c3, w);
        float sendB = lv ? s0 : s1;
        float keepB = lv ? s1 : s0;
        float rB = keepB + __shfl_xor_sync(FULLMASK, sendB, 1);
        rB += __shfl_xor_sync(FULLMASK, rB, 2);

        if (lane4 < 2) {
            if (eA < n_edges)
                outf[2 * (size_t)eA + lv] = rA + puA + pvA + bsel;
            if (eB < n_edges)
                outf[2 * (size_t)eB + lv] = rB + puB + pvB + bsel;
        }

        int kk = k + STAGES;
        if (lane == 0 && kk < K) {
            int tn = stream + kk * NS;
            long long rem = (long long)n_edges - (long long)tn * WTILE_EDGES;
            uint32_t bytes = rem >= WTILE_EDGES
                ? (uint32_t)WTILE_BYTES : (uint32_t)(rem * E_DIM * 4);
            mbar_expect_tx(wmbar + 8 * stage, bytes);
            bulk_copy_g2s(wdata + stage * WTILE_BYTES,
                          ef + (size_t)tn * WTILE_EDGES * E_DIM,
                          bytes, wmbar + 8 * stage);
        }

        if (++stage == STAGES) { stage = 0; parity ^= 1u; }
    }
}

extern "C" void kernel_launch(void* const* d_in, const int* in_sizes, int n_in,
                              void* d_out, int out_size) {
    const float* node_feats = (const float*)d_in[0];
    const float* edge_feats = (const float*)d_in[1];
    const int*   src        = (const int*)d_in[2];
    const int*   dst        = (const int*)d_in[3];
    const float* W          = (const float*)d_in[4];
    const float* b          = (const float*)d_in[5];
    float* outf = (float*)d_out;

    int n_nodes = in_sizes[0] / D_DIM;
    int n_edges = in_sizes[2];
    int n_wtiles = (n_edges + WTILE_EDGES - 1) / WTILE_EDGES;

    static int smem_set = 0;
    if (!smem_set) {
        cudaFuncSetAttribute(fused_kernel,
                             cudaFuncAttributeMaxDynamicSharedMemorySize,
                             SMEM_TOTAL);
        smem_set = 1;
    }

    int threads = 256;
    int blocks = 296;  // 148 SMs * 2 resident blocks = exactly one wave
    int max_blocks = (n_wtiles + WARPS - 1) / WARPS;
    if (blocks > max_blocks) blocks = max_blocks;
    if (blocks < 1) blocks = 1;

    fused_kernel<<<blocks, threads, SMEM_TOTAL>>>(
        node_feats, edge_feats, src, dst, W, b, outf,
        n_nodes, n_edges, n_wtiles);
}

// round 15
// speedup vs baseline: 1.0074x; 1.0074x over previous
#include <cuda_runtime.h>
#include <cstdint>

// Scratch: per-node projection (pu0, pu1, pv0, pv1). 50000 * 16B = 800 KB.
#define MAX_NODES 131072
__device__ float4 g_node_proj[MAX_NODES];

// Device-wide barrier ticket counter (epoch-based: safe across graph replays).
__device__ unsigned long long g_bar;

#define D_DIM 128
#define E_DIM 64
#define FULLMASK 0xffffffffu

// Per-warp pipeline geometry: each warp owns STAGES private 16-edge tiles.
#define WTILE_EDGES 16
#define WTILE_BYTES (WTILE_EDGES * E_DIM * 4)   // 4096
#define STAGES 3
#define WARPS 8
#define SMEM_DATA_BYTES (WARPS * STAGES * WTILE_BYTES)  // 96 KB
#define SMEM_MBAR_OFF SMEM_DATA_BYTES
#define SMEM_TOTAL (SMEM_MBAR_OFF + WARPS * STAGES * 8)

// ---------------------------------------------------------------------------
// PTX helpers
__device__ __forceinline__ uint32_t smem_u32(const void* p) {
    return (uint32_t)__cvta_generic_to_shared(p);
}
__device__ __forceinline__ void mbar_init(uint32_t mbar, uint32_t count) {
    asm volatile("mbarrier.init.shared.b64 [%0], %1;" :: "r"(mbar), "r"(count) : "memory");
}
__device__ __forceinline__ void mbar_expect_tx(uint32_t mbar, uint32_t bytes) {
    asm volatile("mbarrier.arrive.expect_tx.shared.b64 _, [%0], %1;"
                 :: "r"(mbar), "r"(bytes) : "memory");
}
__device__ __forceinline__ void mbar_wait(uint32_t mbar, uint32_t parity) {
    asm volatile(
        "{\n\t"
        ".reg .pred P;\n\t"
        "WAIT_%=:\n\t"
        "mbarrier.try_wait.parity.acquire.cta.shared::cta.b64 P, [%0], %1, 0x989680;\n\t"
        "@!P bra WAIT_%=;\n\t"
        "}"
        :: "r"(mbar), "r"(parity) : "memory");
}
__device__ __forceinline__ void bulk_copy_g2s(uint32_t sdst, const void* gsrc,
                                              uint32_t bytes, uint32_t mbar) {
    asm volatile(
        "cp.async.bulk.shared::cta.global.mbarrier::complete_tx::bytes [%0], [%1], %2, [%3];"
        :: "r"(sdst), "l"(gsrc), "r"(bytes), "r"(mbar) : "memory");
}

// ---------------------------------------------------------------------------
__device__ __forceinline__ void dot16(float& s0, float& s1,
                                      const float4& v0, const float4& v1,
                                      const float4& v2, const float4& v3,
                                      const float2* __restrict__ w) {
    float x0, x1, y0, y1;
    x0 = v0.x * w[0].x;              x1 = v0.x * w[0].y;
    y0 = v2.x * w[8].x;              y1 = v2.x * w[8].y;
    x0 = fmaf(v0.y, w[1].x, x0);     x1 = fmaf(v0.y, w[1].y, x1);
    y0 = fmaf(v2.y, w[9].x, y0);     y1 = fmaf(v2.y, w[9].y, y1);
    x0 = fmaf(v0.z, w[2].x, x0);     x1 = fmaf(v0.z, w[2].y, x1);
    y0 = fmaf(v2.z, w[10].x, y0);    y1 = fmaf(v2.z, w[10].y, y1);
    x0 = fmaf(v0.w, w[3].x, x0);     x1 = fmaf(v0.w, w[3].y, x1);
    y0 = fmaf(v2.w, w[11].x, y0);    y1 = fmaf(v2.w, w[11].y, y1);
    x0 = fmaf(v1.x, w[4].x, x0);     x1 = fmaf(v1.x, w[4].y, x1);
    y0 = fmaf(v3.x, w[12].x, y0);    y1 = fmaf(v3.x, w[12].y, y1);
    x0 = fmaf(v1.y, w[5].x, x0);     x1 = fmaf(v1.y, w[5].y, x1);
    y0 = fmaf(v3.y, w[13].x, y0);    y1 = fmaf(v3.y, w[13].y, y1);
    x0 = fmaf(v1.z, w[6].x, x0);     x1 = fmaf(v1.z, w[6].y, x1);
    y0 = fmaf(v3.z, w[14].x, y0);    y1 = fmaf(v3.z, w[14].y, y1);
    x0 = fmaf(v1.w, w[7].x, x0);     x1 = fmaf(v1.w, w[7].y, x1);
    y0 = fmaf(v3.w, w[15].x, y0);    y1 = fmaf(v3.w, w[15].y, y1);
    s0 = x0 + y0;
    s1 = x1 + y1;
}

// ---------------------------------------------------------------------------
// Fused kernel:
//   Phase 0: mbarrier init + edge TMA prologue (independent of node proj).
//   Phase 1: node projection, SOFTWARE-PIPELINED (prefetch next node rows).
//   Device-wide epoch barrier.
//   Phase 2: per-warp TMA-pipelined edge scoring (R13 layout).
__global__ __launch_bounds__(256, 2)
void fused_kernel(const float* __restrict__ nf,
                  const float* __restrict__ ef,
                  const int* __restrict__ src,
                  const int* __restrict__ dst,
                  const float* __restrict__ W,
                  const float* __restrict__ b,
                  float* __restrict__ outf,
                  int n_nodes, int n_edges, int n_wtiles) {
    extern __shared__ char smem[];
    const uint32_t smem_base = smem_u32(smem);

    const int tid = threadIdx.x;
    const int warp = tid >> 5;
    const int lane = tid & 31;
    const int last = n_edges - 1;

    const uint32_t wdata = smem_base + (uint32_t)(warp * STAGES) * WTILE_BYTES;
    const uint32_t wmbar = smem_base + SMEM_MBAR_OFF + (uint32_t)(warp * STAGES) * 8;

    // ---- Phase 0: mbarrier init + edge prologue TMA (no proj dependency) ----
    if (tid < WARPS * STAGES)
        mbar_init(smem_base + SMEM_MBAR_OFF + tid * 8, 1);
    __syncthreads();

    const int stream = blockIdx.x * WARPS + warp;
    const int NS = gridDim.x * WARPS;
    int K = 0;
    for (int t = stream; t < n_wtiles; t += NS) K++;

    if (lane == 0) {
#pragma unroll
        for (int j = 0; j < STAGES; j++) {
            if (j < K) {
                int t = stream + j * NS;
                long long rem = (long long)n_edges - (long long)t * WTILE_EDGES;
                uint32_t bytes = rem >= WTILE_EDGES
                    ? (uint32_t)WTILE_BYTES : (uint32_t)(rem * E_DIM * 4);
                mbar_expect_tx(wmbar + 8 * j, bytes);
                bulk_copy_g2s(wdata + j * WTILE_BYTES,
                              ef + (size_t)t * WTILE_EDGES * E_DIM,
                              bytes, wmbar + 8 * j);
            }
        }
    }

    // ---- Phase 1: node projection (pipelined: prefetch next iteration) ----
    {
        const int lane16 = tid & 15;
        const int ng = tid >> 4;  // 0..15 node slot within block
        const float2* W2 = reinterpret_cast<const float2*>(W);

        float4 wu_lo0 = *reinterpret_cast<const float4*>(&W2[4 * lane16]);
        float4 wu_lo1 = *reinterpret_cast<const float4*>(&W2[4 * lane16 + 2]);
        float4 wu_hi0 = *reinterpret_cast<const float4*>(&W2[64 + 4 * lane16]);
        float4 wu_hi1 = *reinterpret_cast<const float4*>(&W2[64 + 4 * lane16 + 2]);
        float4 wv_lo0 = *reinterpret_cast<const float4*>(&W2[128 + 4 * lane16]);
        float4 wv_lo1 = *reinterpret_cast<const float4*>(&W2[128 + 4 * lane16 + 2]);
        float4 wv_hi0 = *reinterpret_cast<const float4*>(&W2[192 + 4 * lane16]);
        float4 wv_hi1 = *reinterpret_cast<const float4*>(&W2[192 + 4 * lane16 + 2]);

        const int nstep = gridDim.x * 16;
        int node = blockIdx.x * 16 + ng;
        int node_c = node < n_nodes ? node : (n_nodes - 1);

        // Prologue load.
        const float4* row0 =
            reinterpret_cast<const float4*>(nf + (size_t)node_c * D_DIM);
        float4 a = __ldcs(row0 + lane16);
        float4 c = __ldcs(row0 + lane16 + 16);

        while (node - ng < n_nodes) {  // warp-uniform condition (base < n_nodes)
            // Prefetch next node's rows (clamped).
            int noden = node + nstep;
            int noden_c = noden < n_nodes ? noden : (n_nodes - 1);
            const float4* rown =
                reinterpret_cast<const float4*>(nf + (size_t)noden_c * D_DIM);
            float4 an = __ldcs(rown + lane16);
            float4 cn = __ldcs(rown + lane16 + 16);

            float pu0, pu1, pv0, pv1;
            pu0 = a.x * wu_lo0.x;            pu1 = a.x * wu_lo0.y;
            pv0 = a.x * wv_lo0.x;            pv1 = a.x * wv_lo0.y;
            pu0 = fmaf(a.y, wu_lo0.z, pu0);  pu1 = fmaf(a.y, wu_lo0.w, pu1);
            pv0 = fmaf(a.y, wv_lo0.z, pv0);  pv1 = fmaf(a.y, wv_lo0.w, pv1);
            pu0 = fmaf(a.z, wu_lo1.x, pu0);  pu1 = fmaf(a.z, wu_lo1.y, pu1);
            pv0 = fmaf(a.z, wv_lo1.x, pv0);  pv1 = fmaf(a.z, wv_lo1.y, pv1);
            pu0 = fmaf(a.w, wu_lo1.z, pu0);  pu1 = fmaf(a.w, wu_lo1.w, pu1);
            pv0 = fmaf(a.w, wv_lo1.z, pv0);  pv1 = fmaf(a.w, wv_lo1.w, pv1);
            pu0 = fmaf(c.x, wu_hi0.x, pu0);  pu1 = fmaf(c.x, wu_hi0.y, pu1);
            pv0 = fmaf(c.x, wv_hi0.x, pv0);  pv1 = fmaf(c.x, wv_hi0.y, pv1);
            pu0 = fmaf(c.y, wu_hi0.z, pu0);  pu1 = fmaf(c.y, wu_hi0.w, pu1);
            pv0 = fmaf(c.y, wv_hi0.z, pv0);  pv1 = fmaf(c.y, wv_hi0.w, pv1);
            pu0 = fmaf(c.z, wu_hi1.x, pu0);  pu1 = fmaf(c.z, wu_hi1.y, pu1);
            pv0 = fmaf(c.z, wv_hi1.x, pv0);  pv1 = fmaf(c.z, wv_hi1.y, pv1);
            pu0 = fmaf(c.w, wu_hi1.z, pu0);  pu1 = fmaf(c.w, wu_hi1.w, pu1);
            pv0 = fmaf(c.w, wv_hi1.z, pv0);  pv1 = fmaf(c.w, wv_hi1.w, pv1);

            int l1 = lane16 & 1;
            int l2 = lane16 & 2;
            float sendu = l1 ? pu0 : pu1;
            float keepu = l1 ? pu1 : pu0;
            float ru = keepu + __shfl_xor_sync(FULLMASK, sendu, 1);
            float sendv = l1 ? pv0 : pv1;
            float keepv = l1 ? pv1 : pv0;
            float rv = keepv + __shfl_xor_sync(FULLMASK, sendv, 1);
            float send2 = l2 ? ru : rv;
            float keep2 = l2 ? rv : ru;
            float r = keep2 + __shfl_xor_sync(FULLMASK, send2, 2);
            r += __shfl_xor_sync(FULLMASK, r, 4);
            r += __shfl_xor_sync(FULLMASK, r, 8);

            if (node < n_nodes && lane16 < 4)
                reinterpret_cast<float*>(&g_node_proj[node])[lane16] = r;

            a = an; c = cn;
            node = noden;
        }
    }

    // ---- Device-wide epoch barrier (all blocks co-resident: 2/SM, 1 wave) ----
    __syncthreads();
    if (tid == 0) {
        __threadfence();  // release proj writes
        unsigned long long ticket = atomicAdd(&g_bar, 1ULL);
        unsigned long long target =
            (ticket / (unsigned long long)gridDim.x + 1ULL) *
            (unsigned long long)gridDim.x;
        while (atomicAdd(&g_bar, 0ULL) < target) {
            __nanosleep(64);
        }
        __threadfence();  // acquire
    }
    __syncthreads();

    // ---- Phase 2: edge scoring (R13 per-warp pipeline) ----
    if (K == 0) return;

    const int g8 = lane >> 2;
    const int lane4 = lane & 3;
    const int lv = lane4 & 1;

    const float2* W2 = reinterpret_cast<const float2*>(W);
    float2 w[16];
#pragma unroll
    for (int i = 0; i < 4; i++) {
        int kb = 2 * D_DIM + 4 * (lane4 + 4 * i);
        float4 p0 = *reinterpret_cast<const float4*>(&W2[kb]);
        float4 p1 = *reinterpret_cast<const float4*>(&W2[kb + 2]);
        w[4 * i + 0] = make_float2(p0.x, p0.y);
        w[4 * i + 1] = make_float2(p0.z, p0.w);
        w[4 * i + 2] = make_float2(p1.x, p1.y);
        w[4 * i + 3] = make_float2(p1.z, p1.w);
    }
    const float bsel = lv ? b[1] : b[0];

    int base0 = stream * WTILE_EDGES;
    int eA0 = base0 + g8;
    int eB0 = base0 + g8 + 8;
    int ecA = eA0 > last ? last : eA0;
    int ecB = eB0 > last ? last : eB0;
    int siA = src[ecA], diA = dst[ecA];
    int siB = src[ecB], diB = dst[ecB];

    int stage = 0;
    uint32_t parity = 0;
    for (int k = 0; k < K; k++) {
        int t = stream + k * NS;
        int eA = t * WTILE_EDGES + g8;
        int eB = eA + 8;

        float puA = reinterpret_cast<const float*>(&g_node_proj[siA])[lv];
        float pvA = reinterpret_cast<const float*>(&g_node_proj[diA])[2 + lv];
        float puB = reinterpret_cast<const float*>(&g_node_proj[siB])[lv];
        float pvB = reinterpret_cast<const float*>(&g_node_proj[diB])[2 + lv];
        if (k + 1 < K) {
            int bn = (t + NS) * WTILE_EDGES;
            int enA = bn + g8;
            int enB = bn + g8 + 8;
            int ecnA = enA > last ? last : enA;
            int ecnB = enB > last ? last : enB;
            siA = src[ecnA]; diA = dst[ecnA];
            siB = src[ecnB]; diB = dst[ecnB];
        }

        mbar_wait(wmbar + 8 * stage, parity);

        const char* tpA = smem + (size_t)(warp * STAGES + stage) * WTILE_BYTES
                          + g8 * (E_DIM * 4) + lane4 * 16;
        const char* tpB = tpA + 8 * (E_DIM * 4);
        float4 a0 = *reinterpret_cast<const float4*>(tpA);
        float4 a1 = *reinterpret_cast<const float4*>(tpA + 64);
        float4 a2 = *reinterpret_cast<const float4*>(tpA + 128);
        float4 a3 = *reinterpret_cast<const float4*>(tpA + 192);
        float4 c0 = *reinterpret_cast<const float4*>(tpB);
        float4 c1 = *reinterpret_cast<const float4*>(tpB + 64);
        float4 c2 = *reinterpret_cast<const float4*>(tpB + 128);
        float4 c3 = *reinterpret_cast<const float4*>(tpB + 192);

        float s0, s1;
        dot16(s0, s1, a0, a1, a2, a3, w);
        float sendA = lv ? s0 : s1;
        float keepA = lv ? s1 : s0;
        float rA = keepA + __shfl_xor_sync(FULLMASK, sendA, 1);
        rA += __shfl_xor_sync(FULLMASK, rA, 2);

        dot16(s0, s1, c0, c1, c2, c3, w);
        float sendB = lv ? s0 : s1;
        float keepB = lv ? s1 : s0;
        float rB = keepB + __shfl_xor_sync(FULLMASK, sendB, 1);
        rB += __shfl_xor_sync(FULLMASK, rB, 2);

        if (lane4 < 2) {
            if (eA < n_edges)
                outf[2 * (size_t)eA + lv] = rA + puA + pvA + bsel;
            if (eB < n_edges)
                outf[2 * (size_t)eB + lv] = rB + puB + pvB + bsel;
        }

        int kk = k + STAGES;
        if (lane == 0 && kk < K) {
            int tn = stream + kk * NS;
            long long rem = (long long)n_edges - (long long)tn * WTILE_EDGES;
            uint32_t bytes = rem >= WTILE_EDGES
                ? (uint32_t)WTILE_BYTES : (uint32_t)(rem * E_DIM * 4);
            mbar_expect_tx(wmbar + 8 * stage, bytes);
            bulk_copy_g2s(wdata + stage * WTILE_BYTES,
                          ef + (size_t)tn * WTILE_EDGES * E_DIM,
                          bytes, wmbar + 8 * stage);
        }

        if (++stage == STAGES) { stage = 0; parity ^= 1u; }
    }
}

extern "C" void kernel_launch(void* const* d_in, const int* in_sizes, int n_in,
                              void* d_out, int out_size) {
    const float* node_feats = (const float*)d_in[0];
    const float* edge_feats = (const float*)d_in[1];
    const int*   src        = (const int*)d_in[2];
    const int*   dst        = (const int*)d_in[3];
    const float* W          = (const float*)d_in[4];
    const float* b          = (const float*)d_in[5];
    float* outf = (float*)d_out;

    int n_nodes = in_sizes[0] / D_DIM;
    int n_edges = in_sizes[2];
    int n_wtiles = (n_edges + WTILE_EDGES - 1) / WTILE_EDGES;

    static int smem_set = 0;
    if (!smem_set) {
        cudaFuncSetAttribute(fused_kernel,
                             cudaFuncAttributeMaxDynamicSharedMemorySize,
                             SMEM_TOTAL);
        smem_set = 1;
    }

    int threads = 256;
    int blocks = 296;  // 148 SMs * 2 resident blocks = exactly one wave
    int max_blocks = (n_wtiles + WARPS - 1) / WARPS;
    if (blocks > max_blocks) blocks = max_blocks;
    if (blocks < 1) blocks = 1;

    fused_kernel<<<blocks, threads, SMEM_TOTAL>>>(
        node_feats, edge_feats, src, dst, W, b, outf,
        n_nodes, n_edges, n_wtiles);
}

// round 16
// speedup vs baseline: 1.0410x; 1.0334x over previous
#include <cuda_runtime.h>
#include <cstdint>

// Scratch: per-node projection (pu0, pu1, pv0, pv1). 50000 * 16B = 800 KB.
#define MAX_NODES 131072
__device__ float4 g_node_proj[MAX_NODES];

// Device-wide barrier ticket counter (epoch-based: safe across graph replays).
__device__ unsigned long long g_bar;

#define D_DIM 128
#define E_DIM 64
#define FULLMASK 0xffffffffu

// Unified per-warp tile ring: 4 KB tiles, 3 stages.
#define WTILE_EDGES 16
#define WTILE_BYTES 4096
#define NTILE_NODES 8                     // 8 node rows * 512 B = 4096 B
#define STAGES 3
#define WARPS 8
#define SMEM_DATA_BYTES (WARPS * STAGES * WTILE_BYTES)  // 96 KB
#define SMEM_MBAR_OFF SMEM_DATA_BYTES
#define SMEM_TOTAL (SMEM_MBAR_OFF + WARPS * STAGES * 8)

// ---------------------------------------------------------------------------
// PTX helpers
__device__ __forceinline__ uint32_t smem_u32(const void* p) {
    return (uint32_t)__cvta_generic_to_shared(p);
}
__device__ __forceinline__ void mbar_init(uint32_t mbar, uint32_t count) {
    asm volatile("mbarrier.init.shared.b64 [%0], %1;" :: "r"(mbar), "r"(count) : "memory");
}
__device__ __forceinline__ void mbar_expect_tx(uint32_t mbar, uint32_t bytes) {
    asm volatile("mbarrier.arrive.expect_tx.shared.b64 _, [%0], %1;"
                 :: "r"(mbar), "r"(bytes) : "memory");
}
__device__ __forceinline__ void mbar_wait(uint32_t mbar, uint32_t parity) {
    asm volatile(
        "{\n\t"
        ".reg .pred P;\n\t"
        "WAIT_%=:\n\t"
        "mbarrier.try_wait.parity.acquire.cta.shared::cta.b64 P, [%0], %1, 0x989680;\n\t"
        "@!P bra WAIT_%=;\n\t"
        "}"
        :: "r"(mbar), "r"(parity) : "memory");
}
__device__ __forceinline__ void bulk_copy_g2s(uint32_t sdst, const void* gsrc,
                                              uint32_t bytes, uint32_t mbar) {
    asm volatile(
        "cp.async.bulk.shared::cta.global.mbarrier::complete_tx::bytes [%0], [%1], %2, [%3];"
        :: "r"(sdst), "l"(gsrc), "r"(bytes), "r"(mbar) : "memory");
}

// ---------------------------------------------------------------------------
__device__ __forceinline__ void dot16(float& s0, float& s1,
                                      const float4& v0, const float4& v1,
                                      const float4& v2, const float4& v3,
                                      const float2* __restrict__ w) {
    float x0, x1, y0, y1;
    x0 = v0.x * w[0].x;              x1 = v0.x * w[0].y;
    y0 = v2.x * w[8].x;              y1 = v2.x * w[8].y;
    x0 = fmaf(v0.y, w[1].x, x0);     x1 = fmaf(v0.y, w[1].y, x1);
    y0 = fmaf(v2.y, w[9].x, y0);     y1 = fmaf(v2.y, w[9].y, y1);
    x0 = fmaf(v0.z, w[2].x, x0);     x1 = fmaf(v0.z, w[2].y, x1);
    y0 = fmaf(v2.z, w[10].x, y0);    y1 = fmaf(v2.z, w[10].y, y1);
    x0 = fmaf(v0.w, w[3].x, x0);     x1 = fmaf(v0.w, w[3].y, x1);
    y0 = fmaf(v2.w, w[11].x, y0);    y1 = fmaf(v2.w, w[11].y, y1);
    x0 = fmaf(v1.x, w[4].x, x0);     x1 = fmaf(v1.x, w[4].y, x1);
    y0 = fmaf(v3.x, w[12].x, y0);    y1 = fmaf(v3.x, w[12].y, y1);
    x0 = fmaf(v1.y, w[5].x, x0);     x1 = fmaf(v1.y, w[5].y, x1);
    y0 = fmaf(v3.y, w[13].x, y0);    y1 = fmaf(v3.y, w[13].y, y1);
    x0 = fmaf(v1.z, w[6].x, x0);     x1 = fmaf(v1.z, w[6].y, x1);
    y0 = fmaf(v3.z, w[14].x, y0);    y1 = fmaf(v3.z, w[14].y, y1);
    x0 = fmaf(v1.w, w[7].x, x0);     x1 = fmaf(v1.w, w[7].y, x1);
    y0 = fmaf(v3.w, w[15].x, y0);    y1 = fmaf(v3.w, w[15].y, y1);
    s0 = x0 + y0;
    s1 = x1 + y1;
}

// Unified tile source: tiles [0, K_n) are node tiles; [K_n, K) are edge tiles.
__device__ __forceinline__ void tile_src(int k, int K_n,
                                         const float* __restrict__ nf,
                                         const float* __restrict__ ef,
                                         int stream, int NS,
                                         int n_nodes, int n_edges,
                                         const float** gsrc, uint32_t* bytes) {
    if (k < K_n) {
        int t = stream + k * NS;
        long long remn = (long long)n_nodes - (long long)t * NTILE_NODES;
        int rows = remn >= NTILE_NODES ? NTILE_NODES : (int)remn;
        *gsrc = nf + (size_t)t * NTILE_NODES * D_DIM;
        *bytes = (uint32_t)rows * (D_DIM * 4);
    } else {
        int t = stream + (k - K_n) * NS;
        long long rem = (long long)n_edges - (long long)t * WTILE_EDGES;
        *gsrc = ef + (size_t)t * WTILE_EDGES * E_DIM;
        *bytes = rem >= WTILE_EDGES ? (uint32_t)WTILE_BYTES
                                    : (uint32_t)(rem * E_DIM * 4);
    }
}

// ---------------------------------------------------------------------------
__global__ __launch_bounds__(256, 2)
void fused_kernel(const float* __restrict__ nf,
                  const float* __restrict__ ef,
                  const int* __restrict__ src,
                  const int* __restrict__ dst,
                  const float* __restrict__ W,
                  const float* __restrict__ b,
                  float* __restrict__ outf,
                  int n_nodes, int n_edges, int n_ntiles, int n_wtiles) {
    extern __shared__ char smem[];
    const uint32_t smem_base = smem_u32(smem);

    const int tid = threadIdx.x;
    const int warp = tid >> 5;
    const int lane = tid & 31;
    const int last = n_edges - 1;

    const uint32_t wdata = smem_base + (uint32_t)(warp * STAGES) * WTILE_BYTES;
    const uint32_t wmbar = smem_base + SMEM_MBAR_OFF + (uint32_t)(warp * STAGES) * 8;
    const char* wsm = smem + (size_t)(warp * STAGES) * WTILE_BYTES;

    if (tid < WARPS * STAGES)
        mbar_init(smem_base + SMEM_MBAR_OFF + tid * 8, 1);
    __syncthreads();

    const int stream = blockIdx.x * WARPS + warp;
    const int NS = gridDim.x * WARPS;
    int K_n = 0, K_e = 0;
    for (int t = stream; t < n_ntiles; t += NS) K_n++;
    for (int t = stream; t < n_wtiles; t += NS) K_e++;
    const int K = K_n + K_e;

    // ---- Prologue: fill 3 stages from the unified tile stream ----
    if (lane == 0) {
#pragma unroll
        for (int j = 0; j < STAGES; j++) {
            if (j < K) {
                const float* gsrc; uint32_t bytes;
                tile_src(j, K_n, nf, ef, stream, NS, n_nodes, n_edges,
                         &gsrc, &bytes);
                mbar_expect_tx(wmbar + 8 * j, bytes);
                bulk_copy_g2s(wdata + j * WTILE_BYTES, gsrc, bytes, wmbar + 8 * j);
            }
        }
    }

    int stage = 0;
    uint32_t parity = 0;

    // ---- Phase 1: consume node tiles from the ring ----
    {
        const int lane16 = lane & 15;
        const int half = lane >> 4;   // warp handles 2 nodes per step
        const float2* W2 = reinterpret_cast<const float2*>(W);

        float4 wu_lo0 = *reinterpret_cast<const float4*>(&W2[4 * lane16]);
        float4 wu_lo1 = *reinterpret_cast<const float4*>(&W2[4 * lane16 + 2]);
        float4 wu_hi0 = *reinterpret_cast<const float4*>(&W2[64 + 4 * lane16]);
        float4 wu_hi1 = *reinterpret_cast<const float4*>(&W2[64 + 4 * lane16 + 2]);
        float4 wv_lo0 = *reinterpret_cast<const float4*>(&W2[128 + 4 * lane16]);
        float4 wv_lo1 = *reinterpret_cast<const float4*>(&W2[128 + 4 * lane16 + 2]);
        float4 wv_hi0 = *reinterpret_cast<const float4*>(&W2[192 + 4 * lane16]);
        float4 wv_hi1 = *reinterpret_cast<const float4*>(&W2[192 + 4 * lane16 + 2]);

        for (int k = 0; k < K_n; k++) {
            int t = stream + k * NS;
            int node_base = t * NTILE_NODES;

            mbar_wait(wmbar + 8 * stage, parity);
            const char* sp = wsm + (size_t)stage * WTILE_BYTES;

#pragma unroll
            for (int step = 0; step < 4; step++) {
                int row = 2 * step + half;
                int node = node_base + row;
                const char* rp = sp + row * (D_DIM * 4) + lane16 * 16;
                float4 a = *reinterpret_cast<const float4*>(rp);
                float4 c = *reinterpret_cast<const float4*>(rp + 256);

                float pu0, pu1, pv0, pv1;
                pu0 = a.x * wu_lo0.x;            pu1 = a.x * wu_lo0.y;
                pv0 = a.x * wv_lo0.x;            pv1 = a.x * wv_lo0.y;
                pu0 = fmaf(a.y, wu_lo0.z, pu0);  pu1 = fmaf(a.y, wu_lo0.w, pu1);
                pv0 = fmaf(a.y, wv_lo0.z, pv0);  pv1 = fmaf(a.y, wv_lo0.w, pv1);
                pu0 = fmaf(a.z, wu_lo1.x, pu0);  pu1 = fmaf(a.z, wu_lo1.y, pu1);
                pv0 = fmaf(a.z, wv_lo1.x, pv0);  pv1 = fmaf(a.z, wv_lo1.y, pv1);
                pu0 = fmaf(a.w, wu_lo1.z, pu0);  pu1 = fmaf(a.w, wu_lo1.w, pu1);
                pv0 = fmaf(a.w, wv_lo1.z, pv0);  pv1 = fmaf(a.w, wv_lo1.w, pv1);
                pu0 = fmaf(c.x, wu_hi0.x, pu0);  pu1 = fmaf(c.x, wu_hi0.y, pu1);
                pv0 = fmaf(c.x, wv_hi0.x, pv0);  pv1 = fmaf(c.x, wv_hi0.y, pv1);
                pu0 = fmaf(c.y, wu_hi0.z, pu0);  pu1 = fmaf(c.y, wu_hi0.w, pu1);
                pv0 = fmaf(c.y, wv_hi0.z, pv0);  pv1 = fmaf(c.y, wv_hi0.w, pv1);
                pu0 = fmaf(c.z, wu_hi1.x, pu0);  pu1 = fmaf(c.z, wu_hi1.y, pu1);
                pv0 = fmaf(c.z, wv_hi1.x, pv0);  pv1 = fmaf(c.z, wv_hi1.y, pv1);
                pu0 = fmaf(c.w, wu_hi1.z, pu0);  pu1 = fmaf(c.w, wu_hi1.w, pu1);
                pv0 = fmaf(c.w, wv_hi1.z, pv0);  pv1 = fmaf(c.w, wv_hi1.w, pv1);

                int l1 = lane16 & 1;
                int l2 = lane16 & 2;
                float sendu = l1 ? pu0 : pu1;
                float keepu = l1 ? pu1 : pu0;
                float ru = keepu + __shfl_xor_sync(FULLMASK, sendu, 1);
                float sendv = l1 ? pv0 : pv1;
                float keepv = l1 ? pv1 : pv0;
                float rv = keepv + __shfl_xor_sync(FULLMASK, sendv, 1);
                float send2 = l2 ? ru : rv;
                float keep2 = l2 ? rv : ru;
                float r = keep2 + __shfl_xor_sync(FULLMASK, send2, 2);
                r += __shfl_xor_sync(FULLMASK, r, 4);
                r += __shfl_xor_sync(FULLMASK, r, 8);

                if (node < n_nodes && lane16 < 4)
                    reinterpret_cast<float*>(&g_node_proj[node])[lane16] = r;
            }

            // Refill this stage with tile k+STAGES (may be an edge tile —
            // ef data has no proj dependency, so this overlaps the barrier).
            int kk = k + STAGES;
            if (lane == 0 && kk < K) {
                const float* gsrc; uint32_t bytes;
                tile_src(kk, K_n, nf, ef, stream, NS, n_nodes, n_edges,
                         &gsrc, &bytes);
                mbar_expect_tx(wmbar + 8 * stage, bytes);
                bulk_copy_g2s(wdata + stage * WTILE_BYTES, gsrc, bytes,
                              wmbar + 8 * stage);
            }
            if (++stage == STAGES) { stage = 0; parity ^= 1u; }
        }
    }

    // ---- Edge idx prologue (independent of proj; issue before barrier) ----
    const int g8 = lane >> 2;
    const int lane4 = lane & 3;
    const int lv = lane4 & 1;
    int siA = 0, diA = 0, siB = 0, diB = 0;
    if (K_e > 0) {
        int base0 = stream * WTILE_EDGES;
        int eA0 = base0 + g8;
        int eB0 = base0 + g8 + 8;
        int ecA = eA0 > last ? last : eA0;
        int ecB = eB0 > last ? last : eB0;
        siA = src[ecA]; diA = dst[ecA];
        siB = src[ecB]; diB = dst[ecB];
    }

    // ---- Device-wide epoch barrier (TMA keeps streaming ef during wait) ----
    __syncthreads();
    if (tid == 0) {
        __threadfence();  // release proj writes
        unsigned long long ticket = atomicAdd(&g_bar, 1ULL);
        unsigned long long target =
            (ticket / (unsigned long long)gridDim.x + 1ULL) *
            (unsigned long long)gridDim.x;
        while (atomicAdd(&g_bar, 0ULL) < target) {
            __nanosleep(64);
        }
        __threadfence();  // acquire
    }
    __syncthreads();

    // ---- Phase 2: consume edge tiles from the ring ----
    if (K_e == 0) return;

    const float2* W2 = reinterpret_cast<const float2*>(W);
    float2 w[16];
#pragma unroll
    for (int i = 0; i < 4; i++) {
        int kb = 2 * D_DIM + 4 * (lane4 + 4 * i);
        float4 p0 = *reinterpret_cast<const float4*>(&W2[kb]);
        float4 p1 = *reinterpret_cast<const float4*>(&W2[kb + 2]);
        w[4 * i + 0] = make_float2(p0.x, p0.y);
        w[4 * i + 1] = make_float2(p0.z, p0.w);
        w[4 * i + 2] = make_float2(p1.x, p1.y);
        w[4 * i + 3] = make_float2(p1.z, p1.w);
    }
    const float bsel = lv ? b[1] : b[0];

    for (int ke = 0; ke < K_e; ke++) {
        int k = K_n + ke;
        int t = stream + ke * NS;
        int eA = t * WTILE_EDGES + g8;
        int eB = eA + 8;

        float puA = reinterpret_cast<const float*>(&g_node_proj[siA])[lv];
        float pvA = reinterpret_cast<const float*>(&g_node_proj[diA])[2 + lv];
        float puB = reinterpret_cast<const float*>(&g_node_proj[siB])[lv];
        float pvB = reinterpret_cast<const float*>(&g_node_proj[diB])[2 + lv];
        if (ke + 1 < K_e) {
            int bn = (t + NS) * WTILE_EDGES;
            int enA = bn + g8;
            int enB = bn + g8 + 8;
            int ecnA = enA > last ? last : enA;
            int ecnB = enB > last ? last : enB;
            siA = src[ecnA]; diA = dst[ecnA];
            siB = src[ecnB]; diB = dst[ecnB];
        }

        mbar_wait(wmbar + 8 * stage, parity);

        const char* tpA = wsm + (size_t)stage * WTILE_BYTES
                          + g8 * (E_DIM * 4) + lane4 * 16;
        const char* tpB = tpA + 8 * (E_DIM * 4);
        float4 a0 = *reinterpret_cast<const float4*>(tpA);
        float4 a1 = *reinterpret_cast<const float4*>(tpA + 64);
        float4 a2 = *reinterpret_cast<const float4*>(tpA + 128);
        float4 a3 = *reinterpret_cast<const float4*>(tpA + 192);
        float4 c0 = *reinterpret_cast<const float4*>(tpB);
        float4 c1 = *reinterpret_cast<const float4*>(tpB + 64);
        float4 c2 = *reinterpret_cast<const float4*>(tpB + 128);
        float4 c3 = *reinterpret_cast<const float4*>(tpB + 192);

        float s0, s1;
        dot16(s0, s1, a0, a1, a2, a3, w);
        float sendA = lv ? s0 : s1;
        float keepA = lv ? s1 : s0;
        float rA = keepA + __shfl_xor_sync(FULLMASK, sendA, 1);
        rA += __shfl_xor_sync(FULLMASK, rA, 2);

        dot16(s0, s1, c0, c1, c2, c3, w);
        float sendB = lv ? s0 : s1;
        float keepB = lv ? s1 : s0;
        float rB = keepB + __shfl_xor_sync(FULLMASK, sendB, 1);
        rB += __shfl_xor_sync(FULLMASK, rB, 2);

        if (lane4 < 2) {
            if (eA < n_edges)
                outf[2 * (size_t)eA + lv] = rA + puA + pvA + bsel;
            if (eB < n_edges)
                outf[2 * (size_t)eB + lv] = rB + puB + pvB + bsel;
        }

        int kk = k + STAGES;
        if (lane == 0 && kk < K_n + K_e) {
            const float* gsrc; uint32_t bytes;
            tile_src(kk, K_n, nf, ef, stream, NS, n_nodes, n_edges,
                     &gsrc, &bytes);
            mbar_expect_tx(wmbar + 8 * stage, bytes);
            bulk_copy_g2s(wdata + stage * WTILE_BYTES, gsrc, bytes,
                          wmbar + 8 * stage);
        }

        if (++stage == STAGES) { stage = 0; parity ^= 1u; }
    }
}

extern "C" void kernel_launch(void* const* d_in, const int* in_sizes, int n_in,
                              void* d_out, int out_size) {
    const float* node_feats = (const float*)d_in[0];
    const float* edge_feats = (const float*)d_in[1];
    const int*   src        = (const int*)d_in[2];
    const int*   dst        = (const int*)d_in[3];
    const float* W          = (const float*)d_in[4];
    const float* b          = (const float*)d_in[5];
    float* outf = (float*)d_out;

    int n_nodes = in_sizes[0] / D_DIM;
    int n_edges = in_sizes[2];
    int n_ntiles = (n_nodes + NTILE_NODES - 1) / NTILE_NODES;
    int n_wtiles = (n_edges + WTILE_EDGES - 1) / WTILE_EDGES;

    static int smem_set = 0;
    if (!smem_set) {
        cudaFuncSetAttribute(fused_kernel,
                             cudaFuncAttributeMaxDynamicSharedMemorySize,
                             SMEM_TOTAL);
        smem_set = 1;
    }

    int threads = 256;
    int blocks = 296;  // 148 SMs * 2 resident blocks = exactly one wave
    if (blocks < 1) blocks = 1;

    fused_kernel<<<blocks, threads, SMEM_TOTAL>>>(
        node_feats, edge_feats, src, dst, W, b, outf,
        n_nodes, n_edges, n_ntiles, n_wtiles);
}